// round 12
// baseline (speedup 1.0000x reference)
#include <cuda_runtime.h>
#include <math.h>

#define BB 8
#define NNODE 256
#define FF 512
#define HH 256
#define MM 2048
#define M2 4096
#define NMAT 65536
#define OUT_MAT 524288

typedef unsigned u32;
typedef unsigned long long ull;

// ---------------- scratch ----------------
__device__ float g_x1[M2*HH];
__device__ float g_h [M2*HH];
__device__ float g_ac[M2*HH];
__device__ float g_partial[2*256];
__device__ u32  g_cnt;

__device__ __forceinline__ u32 pack_bf16(float lo, float hi) {
    u32 d; asm("cvt.rn.bf16x2.f32 %0, %1, %2;" : "=r"(d) : "f"(hi), "f"(lo)); return d;
}
__device__ __forceinline__ u32 smaddr(const void* p) {
    u32 a;
    asm("{.reg .u64 t; cvta.to.shared.u64 t, %1; cvt.u32.u64 %0, t;}" : "=r"(a) : "l"(p));
    return a;
}
#define LDSM4(r0,r1,r2,r3,a) \
    asm volatile("ldmatrix.sync.aligned.m8n8.x4.shared.b16 {%0,%1,%2,%3}, [%4];" \
        : "=r"(r0),"=r"(r1),"=r"(r2),"=r"(r3) : "r"(a))
#define LDSM4T(r0,r1,r2,r3,a) \
    asm volatile("ldmatrix.sync.aligned.m8n8.x4.trans.shared.b16 {%0,%1,%2,%3}, [%4];" \
        : "=r"(r0),"=r"(r1),"=r"(r2),"=r"(r3) : "r"(a))
#define MMA_BF16(acc,a0,a1,a2,a3,b0,b1) \
    asm volatile("mma.sync.aligned.m16n8k16.row.col.f32.bf16.bf16.f32 " \
        "{%0,%1,%2,%3}, {%4,%5,%6,%7}, {%8,%9}, {%0,%1,%2,%3};" \
        : "+f"((acc)[0]),"+f"((acc)[1]),"+f"((acc)[2]),"+f"((acc)[3]) \
        : "r"(a0),"r"(a1),"r"(a2),"r"(a3),"r"(b0),"r"(b1))

// ---------------- bf16 tensor-core batched GEMM (unchanged + PDL) ----------------
__global__ __launch_bounds__(256) void gemm2_bf16(
    const float* __restrict__ A0, const float* __restrict__ A1,
    const float* __restrict__ W0, const float* __restrict__ W1,
    const float* __restrict__ b0, const float* __restrict__ b1,
    float* __restrict__ C, int K, int do_relu)
{
    __shared__ __align__(16) u32 AsU[2][2048];
    __shared__ __align__(16) u32 WsU[2][1024];

    const int tid = threadIdx.x;
    const int warp = tid >> 5, lane = tid & 31;
    const int g   = lane >> 2;
    const int tig = lane & 3;
    const int wm  = warp >> 1;
    const int wn  = warp & 1;

    const int half = gridDim.x >> 1;
    const float* A; const float* W; const float* bias;
    int row0;
    if (blockIdx.x < half) { A = A0; W = W0; bias = b0; row0 = blockIdx.x << 7; }
    else                   { A = A1; W = W1; bias = b1; row0 = (blockIdx.x - half) << 7; }
    const int bn = blockIdx.y << 6;
    const int crow0 = blockIdx.x << 7;

    const int wk  = tid >> 3;
    const int wg  = tid & 7;

    float4 ra0[2], ra1[2], rw0, rw1;
    auto load_regs_W = [&](int k0) {
        const float* wp = W + (size_t)(k0 + wk) * HH + bn + (wg << 3);
        rw0 = *reinterpret_cast<const float4*>(wp);
        rw1 = *reinterpret_cast<const float4*>(wp + 4);
    };
    auto load_regs_A = [&](int k0) {
        #pragma unroll
        for (int i = 0; i < 2; ++i) {
            int gi = tid + (i << 8);
            int row = gi >> 2, kg = gi & 3;
            const float* ap = A + (size_t)(row0 + row) * K + k0 + (kg << 3);
            ra0[i] = *reinterpret_cast<const float4*>(ap);
            ra1[i] = *reinterpret_cast<const float4*>(ap + 4);
        }
    };
    auto store_smem = [&](int s) {
        #pragma unroll
        for (int i = 0; i < 2; ++i) {
            int gi = tid + (i << 8);
            int row = gi >> 2, kg = gi & 3;
            int pg = kg ^ ((row >> 1) & 3);
            uint4 u;
            u.x = pack_bf16(ra0[i].x, ra0[i].y);
            u.y = pack_bf16(ra0[i].z, ra0[i].w);
            u.z = pack_bf16(ra1[i].x, ra1[i].y);
            u.w = pack_bf16(ra1[i].z, ra1[i].w);
            *reinterpret_cast<uint4*>(&AsU[s][(row << 4) + (pg << 2)]) = u;
        }
        {
            int pg = wg ^ (wk & 7);
            uint4 u;
            u.x = pack_bf16(rw0.x, rw0.y);
            u.y = pack_bf16(rw0.z, rw0.w);
            u.z = pack_bf16(rw1.x, rw1.y);
            u.w = pack_bf16(rw1.z, rw1.w);
            *reinterpret_cast<uint4*>(&WsU[s][(wk << 5) + (pg << 2)]) = u;
        }
    };

    const int hi   = lane >> 4;
    const int rowL = (wm << 5) + (lane & 15);
    const int sA   = (rowL >> 1) & 3;
    const u32 aB0  = smaddr(&AsU[0][0]) + rowL * 64 + ((hi ^ sA) << 4);
    const int kL   = lane & 15;
    const int sB   = lane & 7;
    const int ng0  = (wn << 2) + hi;
    const u32 bB0  = smaddr(&WsU[0][0]) + kL * 128 + ((ng0 ^ sB) << 4);

    float acc[2][4][4] = {};

    auto compute = [&](int s) {
        const u32 aOff = (u32)(s * 8192);
        const u32 wOff = (u32)(s * 4096);
        #pragma unroll
        for (int kb = 0; kb < 2; ++kb) {
            const u32 ax = (aB0 ^ (kb << 5)) + aOff;
            const u32 bx = bB0 + wOff + (kb << 11);
            u32 a0[4], a1[4];
            LDSM4(a0[0], a0[1], a0[2], a0[3], ax);
            LDSM4(a1[0], a1[1], a1[2], a1[3], ax + 1024);
            #pragma unroll
            for (int nf16 = 0; nf16 < 2; ++nf16) {
                u32 b[4];
                LDSM4T(b[0], b[1], b[2], b[3], bx ^ (nf16 << 5));
                const int nfa = nf16 << 1;
                MMA_BF16(acc[0][nfa + 0], a0[0], a0[1], a0[2], a0[3], b[0], b[1]);
                MMA_BF16(acc[1][nfa + 0], a1[0], a1[1], a1[2], a1[3], b[0], b[1]);
                MMA_BF16(acc[0][nfa + 1], a0[0], a0[1], a0[2], a0[3], b[2], b[3]);
                MMA_BF16(acc[1][nfa + 1], a1[0], a1[1], a1[2], a1[3], b[2], b[3]);
            }
        }
    };

    load_regs_W(0);
#if __CUDA_ARCH__ >= 900
    cudaGridDependencySynchronize();
#endif
    load_regs_A(0);

    const int nk = K >> 5;
    store_smem(0);
    __syncthreads();

    int cur = 0;
    for (int t = 1; t <= nk; ++t) {
        const bool hn = (t < nk);
        if (hn) { load_regs_W(t << 5); load_regs_A(t << 5); }
        compute(cur);
        if (hn) {
            const int nxt = cur ^ 1;
            store_smem(nxt);
            __syncthreads();
            cur = nxt;
        }
    }

    #pragma unroll
    for (int mf = 0; mf < 2; ++mf) {
        #pragma unroll
        for (int nf = 0; nf < 4; ++nf) {
            const int col = bn + (wn << 5) + (nf << 3) + (tig << 1);
            float bx = 0.f, by = 0.f;
            if (bias) { bx = bias[col]; by = bias[col + 1]; }
            const int r0 = crow0 + (wm << 5) + (mf << 4) + g;
            const int r1 = r0 + 8;
            float v0 = acc[mf][nf][0] + bx, v1 = acc[mf][nf][1] + by;
            float v2 = acc[mf][nf][2] + bx, v3 = acc[mf][nf][3] + by;
            if (do_relu) {
                v0 = fmaxf(v0, 0.f); v1 = fmaxf(v1, 0.f);
                v2 = fmaxf(v2, 0.f); v3 = fmaxf(v3, 0.f);
            }
            float2 o01; o01.x = v0; o01.y = v1;
            float2 o23; o23.x = v2; o23.y = v3;
            *reinterpret_cast<float2*>(C + (size_t)r0 * HH + col) = o01;
            *reinterpret_cast<float2*>(C + (size_t)r1 * HH + col) = o23;
        }
    }
}

// ---------------- pairwise abs kernel: 1024 threads, 2i x 2j per thread ------
// out[b,i,j] = sigmoid( 0.5*(da_i + dc_j + sum_h |a_i,h + c_j,h| w_h) + b2 )
// block 64i x 64j, 32 warps (8/SMSP), chunked 32-h double buffer.
#define ADD2(d,a,b)   asm("add.rn.f32x2 %0,%1,%2;"     : "=l"(d) : "l"(a), "l"(b))
#define FMA2(d,a,b,c) asm("fma.rn.f32x2 %0,%1,%2,%3;"  : "=l"(d) : "l"(a), "l"(b), "l"(c))
#define ABS_MASK 0x7FFFFFFF7FFFFFFFULL
#define ASTR 132
#define CSTR 66

__global__ __launch_bounds__(1024) void pair_abs_kernel(
    const float* __restrict__ Aa, const float* __restrict__ Cc,
    const float* __restrict__ w2, const float* __restrict__ b2p,
    float* __restrict__ out)
{
    __shared__ float  aD[2][32][ASTR];   // [h][2i] dup (a,a)
    __shared__ float  cS[2][32][CSTR];   // [h][j]
    __shared__ float2 wD[HH];            // (w,w)
    __shared__ float  daS[64], dcS[64];

    const int tid = threadIdx.x;
    const int tx  = tid & 31;            // j-pair: j = 2tx, 2tx+1
    const int ty  = tid >> 5;            // 0..31: i-pair: i = 2ty, 2ty+1
    const int i0  = blockIdx.x << 6, j0 = blockIdx.y << 6;
    const int b   = blockIdx.z;

    // --- PDL: w2/b2 are external inputs; stage before dependency sync ---
    if (tid < HH) { float w = w2[tid]; wD[tid] = make_float2(w, w); }
    const float b2v = b2p[0];
#if __CUDA_ARCH__ >= 900
    cudaGridDependencySynchronize();
#endif

    // staging: 64 rows x 32 h, 2 floats per thread (float2 loads)
    const int sRow = tid >> 4;           // 0..63
    const int sh   = (tid & 15) << 1;    // 0,2,...,30

    const float* Ab = Aa + ((size_t)b * NNODE + i0) * HH;
    const float* Cb = Cc + ((size_t)b * NNODE + j0) * HH;

    ull acc0 = 0, acc1 = 0;
    float pa_dot = 0.f, pc_dot = 0.f;

    float2 av, cv;
    auto load_gmem = [&](int h0) {
        av = *reinterpret_cast<const float2*>(Ab + (size_t)sRow * HH + h0 + sh);
        cv = *reinterpret_cast<const float2*>(Cb + (size_t)sRow * HH + h0 + sh);
    };
    auto store_smem = [&](int s, int h0) {
        *reinterpret_cast<float2*>(&aD[s][sh+0][sRow<<1]) = make_float2(av.x, av.x);
        *reinterpret_cast<float2*>(&aD[s][sh+1][sRow<<1]) = make_float2(av.y, av.y);
        cS[s][sh+0][sRow] = cv.x;
        cS[s][sh+1][sRow] = cv.y;
        pa_dot += av.x*wD[h0+sh+0].x + av.y*wD[h0+sh+1].x;
        pc_dot += cv.x*wD[h0+sh+0].x + cv.y*wD[h0+sh+1].x;
    };

    load_gmem(0);
    __syncthreads();            // wD visible
    store_smem(0, 0);
    __syncthreads();

    int cur = 0;
    for (int t = 1; t <= 8; ++t) {
        const bool hn = (t < 8);
        if (hn) load_gmem(t << 5);

        // --- register-pipelined inner loop over 32 h ---
        ulonglong2 aC = *reinterpret_cast<const ulonglong2*>(&aD[cur][0][ty << 2]);
        ull cC = *reinterpret_cast<const ull*>(&cS[cur][0][tx << 1]);
        ull wC = *reinterpret_cast<const ull*>(&wD[(t - 1) << 5]);
        #pragma unroll
        for (int h = 0; h < 32; ++h) {
            ulonglong2 aN; ull cN, wN;
            if (h < 31) {
                aN = *reinterpret_cast<const ulonglong2*>(&aD[cur][h+1][ty << 2]);
                cN = *reinterpret_cast<const ull*>(&cS[cur][h+1][tx << 1]);
                wN = *reinterpret_cast<const ull*>(&wD[((t - 1) << 5) + h + 1]);
            }
            ull s0;
            ADD2(s0, aC.x, cC); s0 &= ABS_MASK; FMA2(acc0, s0, wC, acc0);
            ADD2(s0, aC.y, cC); s0 &= ABS_MASK; FMA2(acc1, s0, wC, acc1);
            aC = aN; cC = cN; wC = wN;
        }

        if (hn) {
            const int nxt = cur ^ 1;
            store_smem(nxt, t << 5);
            __syncthreads();
            cur = nxt;
        }
    }

    // reduce fused dots over the 16 lanes sharing sRow
    {
        float v = pa_dot, u = pc_dot;
        v += __shfl_xor_sync(0xffffffffu, v, 1);
        v += __shfl_xor_sync(0xffffffffu, v, 2);
        v += __shfl_xor_sync(0xffffffffu, v, 4);
        v += __shfl_xor_sync(0xffffffffu, v, 8);
        u += __shfl_xor_sync(0xffffffffu, u, 1);
        u += __shfl_xor_sync(0xffffffffu, u, 2);
        u += __shfl_xor_sync(0xffffffffu, u, 4);
        u += __shfl_xor_sync(0xffffffffu, u, 8);
        if ((tid & 15) == 0) { daS[sRow] = v; dcS[sRow] = u; }
    }
    __syncthreads();

    const float dc0 = dcS[(tx << 1) + 0];
    const float dc1 = dcS[(tx << 1) + 1];
    const int jcol = j0 + (tx << 1);
    ull accs[2] = {acc0, acc1};
    #pragma unroll
    for (int k = 0; k < 2; ++k) {
        const int i = (ty << 1) + k;
        const float dai = daS[i];
        float lo = __uint_as_float((u32)(accs[k] & 0xffffffffu));
        float hi = __uint_as_float((u32)(accs[k] >> 32));
        float2 o;
        o.x = 1.f / (1.f + __expf(-(0.5f * (dai + dc0 + lo) + b2v)));
        o.y = 1.f / (1.f + __expf(-(0.5f * (dai + dc1 + hi) + b2v)));
        *reinterpret_cast<float2*>(out + ((size_t)b * NNODE + i0 + i) * NNODE + jcol) = o;
    }
}

// ---------------- fused invariance reduction (single launch, + PDL) ----------------
__global__ __launch_bounds__(256) void reduce_all(
    const float* __restrict__ causal, float* __restrict__ inv)
{
#if __CUDA_ARCH__ >= 900
    cudaGridDependencySynchronize();
#endif
    const int p = blockIdx.x * 256 + threadIdx.x;
    float x[8];
    #pragma unroll
    for (int b = 0; b < 8; ++b) x[b] = causal[b * NMAT + p];
    float stab = 0.f, s = 0.f;
    #pragma unroll
    for (int b = 0; b < 8; ++b) { stab += fabsf(x[b] - x[(b + 7) & 7]); s += x[b]; }
    const float m = s * 0.125f;
    float var = 0.f;
    #pragma unroll
    for (int b = 0; b < 8; ++b) { float d = x[b] - m; var = fmaf(d, d, var); }
    float sd = sqrtf(var * (1.f / 7.f));

    #pragma unroll
    for (int o = 16; o; o >>= 1) {
        stab += __shfl_down_sync(0xffffffffu, stab, o);
        sd   += __shfl_down_sync(0xffffffffu, sd, o);
    }
    __shared__ float sm[8][2];
    const int wid = threadIdx.x >> 5, lane = threadIdx.x & 31;
    if (lane == 0) { sm[wid][0] = stab; sm[wid][1] = sd; }
    __syncthreads();
    if (threadIdx.x == 0) {
        float a = 0.f, c = 0.f;
        #pragma unroll
        for (int w = 0; w < 8; ++w) { a += sm[w][0]; c += sm[w][1]; }
        g_partial[blockIdx.x * 2 + 0] = a;
        g_partial[blockIdx.x * 2 + 1] = c;
    }

    __shared__ int isLast;
    __threadfence();
    if (threadIdx.x == 0) {
        u32 cdone = atomicAdd(&g_cnt, 1u);
        isLast = (cdone == 255u) ? 1 : 0;
    }
    __syncthreads();
    if (isLast) {
        float a = g_partial[threadIdx.x * 2 + 0];
        float c = g_partial[threadIdx.x * 2 + 1];
        #pragma unroll
        for (int o = 16; o; o >>= 1) {
            a += __shfl_down_sync(0xffffffffu, a, o);
            c += __shfl_down_sync(0xffffffffu, c, o);
        }
        if (lane == 0) { sm[wid][0] = a; sm[wid][1] = c; }
        __syncthreads();
        if (threadIdx.x == 0) {
            float sa = 0.f, sc = 0.f;
            #pragma unroll
            for (int w = 0; w < 8; ++w) { sa += sm[w][0]; sc += sm[w][1]; }
            const float stability   = sa / (8.f * 65536.f);
            const float consistency = sc / 65536.f;
            inv[0] = 1.f - (stability + consistency) * 0.5f;
            g_cnt = 0u;
        }
    }
}

// ---------------- launch (PDL-chained) ----------------
static inline void set_pdl(cudaLaunchConfig_t& cfg, cudaLaunchAttribute* attr) {
    attr[0].id = cudaLaunchAttributeProgrammaticStreamSerialization;
    attr[0].val.programmaticStreamSerializationAllowed = 1;
    cfg.attrs = attr;
    cfg.numAttrs = 1;
}

extern "C" void kernel_launch(void* const* d_in, const int* in_sizes, int n_in,
                              void* d_out, int out_size)
{
    const float* img    = (const float*)d_in[0];
    const float* txt    = (const float*)d_in[1];
    const float* ft_W1  = (const float*)d_in[2];
    const float* ft_b1  = (const float*)d_in[3];
    const float* ft_W2  = (const float*)d_in[4];
    const float* ft_b2  = (const float*)d_in[5];
    const float* sl_W1a = (const float*)d_in[6];
    const float* sl_W1b = (const float*)d_in[7];
    const float* sl_b1  = (const float*)d_in[8];
    const float* sl_W2  = (const float*)d_in[9];
    const float* sl_b2  = (const float*)d_in[10];
    const float* cn_W1a = (const float*)d_in[11];
    const float* cn_W1b = (const float*)d_in[12];
    const float* cn_b1  = (const float*)d_in[13];
    const float* cn_W2  = (const float*)d_in[14];
    const float* cn_b2  = (const float*)d_in[15];

    float* outp      = (float*)d_out;
    float* structure = outp;
    float* causal    = outp + OUT_MAT;
    float* inv       = outp + 2 * OUT_MAT;

    float *x1, *h, *ac;
    cudaGetSymbolAddress((void**)&x1, g_x1);
    cudaGetSymbolAddress((void**)&h,  g_h);
    cudaGetSymbolAddress((void**)&ac, g_ac);

    const dim3 gemm_grid(M2 / 128, HH / 64);            // 32 x 4 = 128 blocks
    const dim3 pair_grid(NNODE / 64, NNODE / 64, BB);   // 4 x 4 x 8 = 128 blocks

    cudaLaunchAttribute attr[1];
    cudaLaunchConfig_t cfg{};
    cfg.stream = 0;
    cfg.dynamicSmemBytes = 0;

    gemm2_bf16<<<gemm_grid, 256>>>(img, txt, ft_W1, ft_W1, ft_b1, ft_b1, x1, FF, 1);

    cfg.gridDim = gemm_grid; cfg.blockDim = dim3(256);
    set_pdl(cfg, attr);
    cudaLaunchKernelEx(&cfg, gemm2_bf16,
        (const float*)x1, (const float*)(x1 + (size_t)MM * HH),
        ft_W2, ft_W2, ft_b2, ft_b2, h, HH, 0);

    cudaLaunchKernelEx(&cfg, gemm2_bf16,
        (const float*)h, (const float*)(h + (size_t)MM * HH),
        sl_W1a, sl_W1b, sl_b1, (const float*)nullptr, ac, HH, 0);

    cfg.gridDim = pair_grid; cfg.blockDim = dim3(1024);
    cudaLaunchKernelEx(&cfg, pair_abs_kernel,
        (const float*)ac, (const float*)(ac + (size_t)MM * HH), sl_W2, sl_b2, structure);

    cfg.gridDim = gemm_grid; cfg.blockDim = dim3(256);
    cudaLaunchKernelEx(&cfg, gemm2_bf16,
        (const float*)structure, (const float*)structure,
        cn_W1a, cn_W1b, cn_b1, (const float*)nullptr, ac, HH, 0);

    cfg.gridDim = pair_grid; cfg.blockDim = dim3(1024);
    cudaLaunchKernelEx(&cfg, pair_abs_kernel,
        (const float*)ac, (const float*)(ac + (size_t)MM * HH), cn_W2, cn_b2, causal);

    cfg.gridDim = dim3(256); cfg.blockDim = dim3(256);
    cudaLaunchKernelEx(&cfg, reduce_all, (const float*)causal, inv);
}

// round 13
// speedup vs baseline: 1.0240x; 1.0240x over previous
#include <cuda_runtime.h>
#include <math.h>

#define BB 8
#define NNODE 256
#define FF 512
#define HH 256
#define MM 2048
#define M2 4096
#define NMAT 65536
#define OUT_MAT 524288

typedef unsigned u32;
typedef unsigned long long ull;

// ---------------- scratch ----------------
__device__ float g_x1[M2*HH];
__device__ float g_h [M2*HH];
__device__ float g_ac[M2*HH];
__device__ float g_partial[2*256];
__device__ u32  g_cnt;

__device__ __forceinline__ u32 pack_bf16(float lo, float hi) {
    u32 d; asm("cvt.rn.bf16x2.f32 %0, %1, %2;" : "=r"(d) : "f"(hi), "f"(lo)); return d;
}
__device__ __forceinline__ u32 smaddr(const void* p) {
    u32 a;
    asm("{.reg .u64 t; cvta.to.shared.u64 t, %1; cvt.u32.u64 %0, t;}" : "=r"(a) : "l"(p));
    return a;
}
#define LDSM4(r0,r1,r2,r3,a) \
    asm volatile("ldmatrix.sync.aligned.m8n8.x4.shared.b16 {%0,%1,%2,%3}, [%4];" \
        : "=r"(r0),"=r"(r1),"=r"(r2),"=r"(r3) : "r"(a))
#define LDSM4T(r0,r1,r2,r3,a) \
    asm volatile("ldmatrix.sync.aligned.m8n8.x4.trans.shared.b16 {%0,%1,%2,%3}, [%4];" \
        : "=r"(r0),"=r"(r1),"=r"(r2),"=r"(r3) : "r"(a))
#define MMA_BF16(acc,a0,a1,a2,a3,b0,b1) \
    asm volatile("mma.sync.aligned.m16n8k16.row.col.f32.bf16.bf16.f32 " \
        "{%0,%1,%2,%3}, {%4,%5,%6,%7}, {%8,%9}, {%0,%1,%2,%3};" \
        : "+f"((acc)[0]),"+f"((acc)[1]),"+f"((acc)[2]),"+f"((acc)[3]) \
        : "r"(a0),"r"(a1),"r"(a2),"r"(a3),"r"(b0),"r"(b1))

// ---------------- bf16 tensor-core batched GEMM (unchanged + PDL) ----------------
__global__ __launch_bounds__(256) void gemm2_bf16(
    const float* __restrict__ A0, const float* __restrict__ A1,
    const float* __restrict__ W0, const float* __restrict__ W1,
    const float* __restrict__ b0, const float* __restrict__ b1,
    float* __restrict__ C, int K, int do_relu)
{
    __shared__ __align__(16) u32 AsU[2][2048];
    __shared__ __align__(16) u32 WsU[2][1024];

    const int tid = threadIdx.x;
    const int warp = tid >> 5, lane = tid & 31;
    const int g   = lane >> 2;
    const int tig = lane & 3;
    const int wm  = warp >> 1;
    const int wn  = warp & 1;

    const int half = gridDim.x >> 1;
    const float* A; const float* W; const float* bias;
    int row0;
    if (blockIdx.x < half) { A = A0; W = W0; bias = b0; row0 = blockIdx.x << 7; }
    else                   { A = A1; W = W1; bias = b1; row0 = (blockIdx.x - half) << 7; }
    const int bn = blockIdx.y << 6;
    const int crow0 = blockIdx.x << 7;

    const int wk  = tid >> 3;
    const int wg  = tid & 7;

    float4 ra0[2], ra1[2], rw0, rw1;
    auto load_regs_W = [&](int k0) {
        const float* wp = W + (size_t)(k0 + wk) * HH + bn + (wg << 3);
        rw0 = *reinterpret_cast<const float4*>(wp);
        rw1 = *reinterpret_cast<const float4*>(wp + 4);
    };
    auto load_regs_A = [&](int k0) {
        #pragma unroll
        for (int i = 0; i < 2; ++i) {
            int gi = tid + (i << 8);
            int row = gi >> 2, kg = gi & 3;
            const float* ap = A + (size_t)(row0 + row) * K + k0 + (kg << 3);
            ra0[i] = *reinterpret_cast<const float4*>(ap);
            ra1[i] = *reinterpret_cast<const float4*>(ap + 4);
        }
    };
    auto store_smem = [&](int s) {
        #pragma unroll
        for (int i = 0; i < 2; ++i) {
            int gi = tid + (i << 8);
            int row = gi >> 2, kg = gi & 3;
            int pg = kg ^ ((row >> 1) & 3);
            uint4 u;
            u.x = pack_bf16(ra0[i].x, ra0[i].y);
            u.y = pack_bf16(ra0[i].z, ra0[i].w);
            u.z = pack_bf16(ra1[i].x, ra1[i].y);
            u.w = pack_bf16(ra1[i].z, ra1[i].w);
            *reinterpret_cast<uint4*>(&AsU[s][(row << 4) + (pg << 2)]) = u;
        }
        {
            int pg = wg ^ (wk & 7);
            uint4 u;
            u.x = pack_bf16(rw0.x, rw0.y);
            u.y = pack_bf16(rw0.z, rw0.w);
            u.z = pack_bf16(rw1.x, rw1.y);
            u.w = pack_bf16(rw1.z, rw1.w);
            *reinterpret_cast<uint4*>(&WsU[s][(wk << 5) + (pg << 2)]) = u;
        }
    };

    const int hi   = lane >> 4;
    const int rowL = (wm << 5) + (lane & 15);
    const int sA   = (rowL >> 1) & 3;
    const u32 aB0  = smaddr(&AsU[0][0]) + rowL * 64 + ((hi ^ sA) << 4);
    const int kL   = lane & 15;
    const int sB   = lane & 7;
    const int ng0  = (wn << 2) + hi;
    const u32 bB0  = smaddr(&WsU[0][0]) + kL * 128 + ((ng0 ^ sB) << 4);

    float acc[2][4][4] = {};

    auto compute = [&](int s) {
        const u32 aOff = (u32)(s * 8192);
        const u32 wOff = (u32)(s * 4096);
        #pragma unroll
        for (int kb = 0; kb < 2; ++kb) {
            const u32 ax = (aB0 ^ (kb << 5)) + aOff;
            const u32 bx = bB0 + wOff + (kb << 11);
            u32 a0[4], a1[4];
            LDSM4(a0[0], a0[1], a0[2], a0[3], ax);
            LDSM4(a1[0], a1[1], a1[2], a1[3], ax + 1024);
            #pragma unroll
            for (int nf16 = 0; nf16 < 2; ++nf16) {
                u32 b[4];
                LDSM4T(b[0], b[1], b[2], b[3], bx ^ (nf16 << 5));
                const int nfa = nf16 << 1;
                MMA_BF16(acc[0][nfa + 0], a0[0], a0[1], a0[2], a0[3], b[0], b[1]);
                MMA_BF16(acc[1][nfa + 0], a1[0], a1[1], a1[2], a1[3], b[0], b[1]);
                MMA_BF16(acc[0][nfa + 1], a0[0], a0[1], a0[2], a0[3], b[2], b[3]);
                MMA_BF16(acc[1][nfa + 1], a1[0], a1[1], a1[2], a1[3], b[2], b[3]);
            }
        }
    };

    load_regs_W(0);
#if __CUDA_ARCH__ >= 900
    cudaGridDependencySynchronize();
#endif
    load_regs_A(0);

    const int nk = K >> 5;
    store_smem(0);
    __syncthreads();

    int cur = 0;
    for (int t = 1; t <= nk; ++t) {
        const bool hn = (t < nk);
        if (hn) { load_regs_W(t << 5); load_regs_A(t << 5); }
        compute(cur);
        if (hn) {
            const int nxt = cur ^ 1;
            store_smem(nxt);
            __syncthreads();
            cur = nxt;
        }
    }

    #pragma unroll
    for (int mf = 0; mf < 2; ++mf) {
        #pragma unroll
        for (int nf = 0; nf < 4; ++nf) {
            const int col = bn + (wn << 5) + (nf << 3) + (tig << 1);
            float bx = 0.f, by = 0.f;
            if (bias) { bx = bias[col]; by = bias[col + 1]; }
            const int r0 = crow0 + (wm << 5) + (mf << 4) + g;
            const int r1 = r0 + 8;
            float v0 = acc[mf][nf][0] + bx, v1 = acc[mf][nf][1] + by;
            float v2 = acc[mf][nf][2] + bx, v3 = acc[mf][nf][3] + by;
            if (do_relu) {
                v0 = fmaxf(v0, 0.f); v1 = fmaxf(v1, 0.f);
                v2 = fmaxf(v2, 0.f); v3 = fmaxf(v3, 0.f);
            }
            float2 o01; o01.x = v0; o01.y = v1;
            float2 o23; o23.x = v2; o23.y = v3;
            *reinterpret_cast<float2*>(C + (size_t)r0 * HH + col) = o01;
            *reinterpret_cast<float2*>(C + (size_t)r1 * HH + col) = o23;
        }
    }
}

// ---------------- pairwise abs kernel: 64i x 32j CTA, 256 thr, 2 CTA/SM ------
// out[b,i,j] = sigmoid( 0.5*(da_i + dc_j + sum_h |a_i,h + c_j,h| w_h) + b2 )
// thread tile 4i x 2j(packed); grid 256 CTAs (2 per SM), chunked 32-h buffer.
#define ADD2(d,a,b)   asm("add.rn.f32x2 %0,%1,%2;"     : "=l"(d) : "l"(a), "l"(b))
#define FMA2(d,a,b,c) asm("fma.rn.f32x2 %0,%1,%2,%3;"  : "=l"(d) : "l"(a), "l"(b), "l"(c))
#define ABS_MASK 0x7FFFFFFF7FFFFFFFULL
#define ASTR 132   // aD row stride (floats)
#define CSTR 34    // cS row stride (floats)

__global__ __launch_bounds__(256) void pair_abs_kernel(
    const float* __restrict__ Aa, const float* __restrict__ Cc,
    const float* __restrict__ w2, const float* __restrict__ b2p,
    float* __restrict__ out)
{
    __shared__ float  aD[2][32][ASTR];   // [h][2i] dup (a,a)
    __shared__ float  cS[2][32][CSTR];   // [h][j] natural (32 j)
    __shared__ float2 wD[HH];            // (w,w)
    __shared__ float  daS[64], dcS[32];

    const int tid = threadIdx.x;
    const int tx  = tid & 15;            // j-pair: j = 2tx, 2tx+1 (0..31)
    const int ty  = tid >> 4;            // 0..15: i = 4ty..4ty+3
    const int i0  = blockIdx.x << 6, j0 = blockIdx.y << 5;
    const int b   = blockIdx.z;

    // --- PDL: w2/b2 are external inputs; stage before dependency sync ---
    { float w = w2[tid]; wD[tid] = make_float2(w, w); }   // 256 threads == HH
    const float b2v = b2p[0];
#if __CUDA_ARCH__ >= 900
    cudaGridDependencySynchronize();
#endif

    // staging maps: a: 64 rows x 32 h (8 floats/thread); c: 32 rows x 32 h (4 floats/thread)
    const int aRow = tid >> 2;           // 0..63
    const int ah   = (tid & 3) << 3;     // 0,8,16,24
    const int cRow = tid >> 3;           // 0..31
    const int ch   = (tid & 7) << 2;     // 0..28

    const float* Ab = Aa + ((size_t)b * NNODE + i0) * HH;
    const float* Cb = Cc + ((size_t)b * NNODE + j0) * HH;

    ull acc0 = 0, acc1 = 0, acc2 = 0, acc3 = 0;
    float pa_dot = 0.f, pc_dot = 0.f;

    float4 av0, av1, cv;
    auto load_gmem = [&](int h0) {
        const float* ap = Ab + (size_t)aRow * HH + h0 + ah;
        av0 = *reinterpret_cast<const float4*>(ap);
        av1 = *reinterpret_cast<const float4*>(ap + 4);
        cv  = *reinterpret_cast<const float4*>(Cb + (size_t)cRow * HH + h0 + ch);
    };
    auto store_smem = [&](int s, int h0) {
        *reinterpret_cast<float2*>(&aD[s][ah+0][aRow<<1]) = make_float2(av0.x, av0.x);
        *reinterpret_cast<float2*>(&aD[s][ah+1][aRow<<1]) = make_float2(av0.y, av0.y);
        *reinterpret_cast<float2*>(&aD[s][ah+2][aRow<<1]) = make_float2(av0.z, av0.z);
        *reinterpret_cast<float2*>(&aD[s][ah+3][aRow<<1]) = make_float2(av0.w, av0.w);
        *reinterpret_cast<float2*>(&aD[s][ah+4][aRow<<1]) = make_float2(av1.x, av1.x);
        *reinterpret_cast<float2*>(&aD[s][ah+5][aRow<<1]) = make_float2(av1.y, av1.y);
        *reinterpret_cast<float2*>(&aD[s][ah+6][aRow<<1]) = make_float2(av1.z, av1.z);
        *reinterpret_cast<float2*>(&aD[s][ah+7][aRow<<1]) = make_float2(av1.w, av1.w);
        cS[s][ch+0][cRow] = cv.x;
        cS[s][ch+1][cRow] = cv.y;
        cS[s][ch+2][cRow] = cv.z;
        cS[s][ch+3][cRow] = cv.w;
        pa_dot += av0.x*wD[h0+ah+0].x + av0.y*wD[h0+ah+1].x
                + av0.z*wD[h0+ah+2].x + av0.w*wD[h0+ah+3].x
                + av1.x*wD[h0+ah+4].x + av1.y*wD[h0+ah+5].x
                + av1.z*wD[h0+ah+6].x + av1.w*wD[h0+ah+7].x;
        pc_dot += cv.x*wD[h0+ch+0].x + cv.y*wD[h0+ch+1].x
                + cv.z*wD[h0+ch+2].x + cv.w*wD[h0+ch+3].x;
    };

    load_gmem(0);
    __syncthreads();            // wD visible
    store_smem(0, 0);
    __syncthreads();

    int cur = 0;
    for (int t = 1; t <= 8; ++t) {
        const bool hn = (t < 8);
        if (hn) load_gmem(t << 5);
        const int hb = (t - 1) << 5;

        // --- register-pipelined inner loop over 32 h ---
        ulonglong2 aC0 = *reinterpret_cast<const ulonglong2*>(&aD[cur][0][ty << 3]);
        ulonglong2 aC1 = *reinterpret_cast<const ulonglong2*>(&aD[cur][0][(ty << 3) + 4]);
        ull cC = *reinterpret_cast<const ull*>(&cS[cur][0][tx << 1]);
        ull wC = *reinterpret_cast<const ull*>(&wD[hb]);
        #pragma unroll
        for (int h = 0; h < 32; ++h) {
            ulonglong2 aN0, aN1; ull cN, wN;
            if (h < 31) {
                aN0 = *reinterpret_cast<const ulonglong2*>(&aD[cur][h+1][ty << 3]);
                aN1 = *reinterpret_cast<const ulonglong2*>(&aD[cur][h+1][(ty << 3) + 4]);
                cN  = *reinterpret_cast<const ull*>(&cS[cur][h+1][tx << 1]);
                wN  = *reinterpret_cast<const ull*>(&wD[hb + h + 1]);
            }
            ull s0;
            ADD2(s0, aC0.x, cC); s0 &= ABS_MASK; FMA2(acc0, s0, wC, acc0);
            ADD2(s0, aC0.y, cC); s0 &= ABS_MASK; FMA2(acc1, s0, wC, acc1);
            ADD2(s0, aC1.x, cC); s0 &= ABS_MASK; FMA2(acc2, s0, wC, acc2);
            ADD2(s0, aC1.y, cC); s0 &= ABS_MASK; FMA2(acc3, s0, wC, acc3);
            aC0 = aN0; aC1 = aN1; cC = cN; wC = wN;
        }

        if (hn) {
            const int nxt = cur ^ 1;
            store_smem(nxt, t << 5);
            __syncthreads();
            cur = nxt;
        }
    }

    // reduce fused dots: pa over tid&3 group (4 lanes), pc over tid&7 group (8 lanes)
    {
        float v = pa_dot;
        v += __shfl_xor_sync(0xffffffffu, v, 1);
        v += __shfl_xor_sync(0xffffffffu, v, 2);
        if ((tid & 3) == 0) daS[aRow] = v;
        float u = pc_dot;
        u += __shfl_xor_sync(0xffffffffu, u, 1);
        u += __shfl_xor_sync(0xffffffffu, u, 2);
        u += __shfl_xor_sync(0xffffffffu, u, 4);
        if ((tid & 7) == 0) dcS[cRow] = u;
    }
    __syncthreads();

    const float dc0 = dcS[(tx << 1) + 0];
    const float dc1 = dcS[(tx << 1) + 1];
    const int jcol = j0 + (tx << 1);
    ull accs[4] = {acc0, acc1, acc2, acc3};
    #pragma unroll
    for (int k = 0; k < 4; ++k) {
        const int i = (ty << 2) + k;
        const float dai = daS[i];
        float lo = __uint_as_float((u32)(accs[k] & 0xffffffffu));
        float hi = __uint_as_float((u32)(accs[k] >> 32));
        float2 o;
        o.x = 1.f / (1.f + __expf(-(0.5f * (dai + dc0 + lo) + b2v)));
        o.y = 1.f / (1.f + __expf(-(0.5f * (dai + dc1 + hi) + b2v)));
        *reinterpret_cast<float2*>(out + ((size_t)b * NNODE + i0 + i) * NNODE + jcol) = o;
    }
}

// ---------------- fused invariance reduction (single launch, + PDL) ----------------
__global__ __launch_bounds__(256) void reduce_all(
    const float* __restrict__ causal, float* __restrict__ inv)
{
#if __CUDA_ARCH__ >= 900
    cudaGridDependencySynchronize();
#endif
    const int p = blockIdx.x * 256 + threadIdx.x;
    float x[8];
    #pragma unroll
    for (int b = 0; b < 8; ++b) x[b] = causal[b * NMAT + p];
    float stab = 0.f, s = 0.f;
    #pragma unroll
    for (int b = 0; b < 8; ++b) { stab += fabsf(x[b] - x[(b + 7) & 7]); s += x[b]; }
    const float m = s * 0.125f;
    float var = 0.f;
    #pragma unroll
    for (int b = 0; b < 8; ++b) { float d = x[b] - m; var = fmaf(d, d, var); }
    float sd = sqrtf(var * (1.f / 7.f));

    #pragma unroll
    for (int o = 16; o; o >>= 1) {
        stab += __shfl_down_sync(0xffffffffu, stab, o);
        sd   += __shfl_down_sync(0xffffffffu, sd, o);
    }
    __shared__ float sm[8][2];
    const int wid = threadIdx.x >> 5, lane = threadIdx.x & 31;
    if (lane == 0) { sm[wid][0] = stab; sm[wid][1] = sd; }
    __syncthreads();
    if (threadIdx.x == 0) {
        float a = 0.f, c = 0.f;
        #pragma unroll
        for (int w = 0; w < 8; ++w) { a += sm[w][0]; c += sm[w][1]; }
        g_partial[blockIdx.x * 2 + 0] = a;
        g_partial[blockIdx.x * 2 + 1] = c;
    }

    __shared__ int isLast;
    __threadfence();
    if (threadIdx.x == 0) {
        u32 cdone = atomicAdd(&g_cnt, 1u);
        isLast = (cdone == 255u) ? 1 : 0;
    }
    __syncthreads();
    if (isLast) {
        float a = g_partial[threadIdx.x * 2 + 0];
        float c = g_partial[threadIdx.x * 2 + 1];
        #pragma unroll
        for (int o = 16; o; o >>= 1) {
            a += __shfl_down_sync(0xffffffffu, a, o);
            c += __shfl_down_sync(0xffffffffu, c, o);
        }
        if (lane == 0) { sm[wid][0] = a; sm[wid][1] = c; }
        __syncthreads();
        if (threadIdx.x == 0) {
            float sa = 0.f, sc = 0.f;
            #pragma unroll
            for (int w = 0; w < 8; ++w) { sa += sm[w][0]; sc += sm[w][1]; }
            const float stability   = sa / (8.f * 65536.f);
            const float consistency = sc / 65536.f;
            inv[0] = 1.f - (stability + consistency) * 0.5f;
            g_cnt = 0u;
        }
    }
}

// ---------------- launch (PDL-chained) ----------------
static inline void set_pdl(cudaLaunchConfig_t& cfg, cudaLaunchAttribute* attr) {
    attr[0].id = cudaLaunchAttributeProgrammaticStreamSerialization;
    attr[0].val.programmaticStreamSerializationAllowed = 1;
    cfg.attrs = attr;
    cfg.numAttrs = 1;
}

extern "C" void kernel_launch(void* const* d_in, const int* in_sizes, int n_in,
                              void* d_out, int out_size)
{
    const float* img    = (const float*)d_in[0];
    const float* txt    = (const float*)d_in[1];
    const float* ft_W1  = (const float*)d_in[2];
    const float* ft_b1  = (const float*)d_in[3];
    const float* ft_W2  = (const float*)d_in[4];
    const float* ft_b2  = (const float*)d_in[5];
    const float* sl_W1a = (const float*)d_in[6];
    const float* sl_W1b = (const float*)d_in[7];
    const float* sl_b1  = (const float*)d_in[8];
    const float* sl_W2  = (const float*)d_in[9];
    const float* sl_b2  = (const float*)d_in[10];
    const float* cn_W1a = (const float*)d_in[11];
    const float* cn_W1b = (const float*)d_in[12];
    const float* cn_b1  = (const float*)d_in[13];
    const float* cn_W2  = (const float*)d_in[14];
    const float* cn_b2  = (const float*)d_in[15];

    float* outp      = (float*)d_out;
    float* structure = outp;
    float* causal    = outp + OUT_MAT;
    float* inv       = outp + 2 * OUT_MAT;

    float *x1, *h, *ac;
    cudaGetSymbolAddress((void**)&x1, g_x1);
    cudaGetSymbolAddress((void**)&h,  g_h);
    cudaGetSymbolAddress((void**)&ac, g_ac);

    const dim3 gemm_grid(M2 / 128, HH / 64);            // 32 x 4 = 128 blocks
    const dim3 pair_grid(NNODE / 64, NNODE / 32, BB);   // 4 x 8 x 8 = 256 blocks

    cudaLaunchAttribute attr[1];
    cudaLaunchConfig_t cfg{};
    cfg.stream = 0;
    cfg.dynamicSmemBytes = 0;

    gemm2_bf16<<<gemm_grid, 256>>>(img, txt, ft_W1, ft_W1, ft_b1, ft_b1, x1, FF, 1);

    cfg.gridDim = gemm_grid; cfg.blockDim = dim3(256);
    set_pdl(cfg, attr);
    cudaLaunchKernelEx(&cfg, gemm2_bf16,
        (const float*)x1, (const float*)(x1 + (size_t)MM * HH),
        ft_W2, ft_W2, ft_b2, ft_b2, h, HH, 0);

    cudaLaunchKernelEx(&cfg, gemm2_bf16,
        (const float*)h, (const float*)(h + (size_t)MM * HH),
        sl_W1a, sl_W1b, sl_b1, (const float*)nullptr, ac, HH, 0);

    cfg.gridDim = pair_grid; cfg.blockDim = dim3(256);
    cudaLaunchKernelEx(&cfg, pair_abs_kernel,
        (const float*)ac, (const float*)(ac + (size_t)MM * HH), sl_W2, sl_b2, structure);

    cfg.gridDim = gemm_grid; cfg.blockDim = dim3(256);
    cudaLaunchKernelEx(&cfg, gemm2_bf16,
        (const float*)structure, (const float*)structure,
        cn_W1a, cn_W1b, cn_b1, (const float*)nullptr, ac, HH, 0);

    cfg.gridDim = pair_grid; cfg.blockDim = dim3(256);
    cudaLaunchKernelEx(&cfg, pair_abs_kernel,
        (const float*)ac, (const float*)(ac + (size_t)MM * HH), cn_W2, cn_b2, causal);

    cfg.gridDim = dim3(256); cfg.blockDim = dim3(256);
    cudaLaunchKernelEx(&cfg, reduce_all, (const float*)causal, inv);
}

// round 14
// speedup vs baseline: 1.1307x; 1.1042x over previous
#include <cuda_runtime.h>
#include <math.h>

#define BB 8
#define NNODE 256
#define FF 512
#define HH 256
#define MM 2048
#define M2 4096
#define NMAT 65536
#define OUT_MAT 524288

typedef unsigned u32;
typedef unsigned long long ull;

// ---------------- scratch ----------------
__device__ float g_x1[M2*HH];
__device__ float g_h [M2*HH];
__device__ float g_ac[M2*HH];
__device__ float g_partial[2*64];
__device__ u32  g_cnt;

__device__ __forceinline__ u32 pack_bf16(float lo, float hi) {
    u32 d; asm("cvt.rn.bf16x2.f32 %0, %1, %2;" : "=r"(d) : "f"(hi), "f"(lo)); return d;
}
__device__ __forceinline__ u32 smaddr(const void* p) {
    u32 a;
    asm("{.reg .u64 t; cvta.to.shared.u64 t, %1; cvt.u32.u64 %0, t;}" : "=r"(a) : "l"(p));
    return a;
}
#define LDSM4(r0,r1,r2,r3,a) \
    asm volatile("ldmatrix.sync.aligned.m8n8.x4.shared.b16 {%0,%1,%2,%3}, [%4];" \
        : "=r"(r0),"=r"(r1),"=r"(r2),"=r"(r3) : "r"(a))
#define LDSM4T(r0,r1,r2,r3,a) \
    asm volatile("ldmatrix.sync.aligned.m8n8.x4.trans.shared.b16 {%0,%1,%2,%3}, [%4];" \
        : "=r"(r0),"=r"(r1),"=r"(r2),"=r"(r3) : "r"(a))
#define MMA_BF16(acc,a0,a1,a2,a3,b0,b1) \
    asm volatile("mma.sync.aligned.m16n8k16.row.col.f32.bf16.bf16.f32 " \
        "{%0,%1,%2,%3}, {%4,%5,%6,%7}, {%8,%9}, {%0,%1,%2,%3};" \
        : "+f"((acc)[0]),"+f"((acc)[1]),"+f"((acc)[2]),"+f"((acc)[3]) \
        : "r"(a0),"r"(a1),"r"(a2),"r"(a3),"r"(b0),"r"(b1))

// ---------------- bf16 tensor-core batched GEMM (R11, unchanged) ----------------
__global__ __launch_bounds__(256) void gemm2_bf16(
    const float* __restrict__ A0, const float* __restrict__ A1,
    const float* __restrict__ W0, const float* __restrict__ W1,
    const float* __restrict__ b0, const float* __restrict__ b1,
    float* __restrict__ C, int K, int do_relu)
{
    __shared__ __align__(16) u32 AsU[2][2048];
    __shared__ __align__(16) u32 WsU[2][1024];

    const int tid = threadIdx.x;
    const int warp = tid >> 5, lane = tid & 31;
    const int g   = lane >> 2;
    const int tig = lane & 3;
    const int wm  = warp >> 1;
    const int wn  = warp & 1;

    const int half = gridDim.x >> 1;
    const float* A; const float* W; const float* bias;
    int row0;
    if (blockIdx.x < half) { A = A0; W = W0; bias = b0; row0 = blockIdx.x << 7; }
    else                   { A = A1; W = W1; bias = b1; row0 = (blockIdx.x - half) << 7; }
    const int bn = blockIdx.y << 6;
    const int crow0 = blockIdx.x << 7;

    const int wk  = tid >> 3;
    const int wg  = tid & 7;

    float4 ra0[2], ra1[2], rw0, rw1;
    auto load_regs_W = [&](int k0) {
        const float* wp = W + (size_t)(k0 + wk) * HH + bn + (wg << 3);
        rw0 = *reinterpret_cast<const float4*>(wp);
        rw1 = *reinterpret_cast<const float4*>(wp + 4);
    };
    auto load_regs_A = [&](int k0) {
        #pragma unroll
        for (int i = 0; i < 2; ++i) {
            int gi = tid + (i << 8);
            int row = gi >> 2, kg = gi & 3;
            const float* ap = A + (size_t)(row0 + row) * K + k0 + (kg << 3);
            ra0[i] = *reinterpret_cast<const float4*>(ap);
            ra1[i] = *reinterpret_cast<const float4*>(ap + 4);
        }
    };
    auto store_smem = [&](int s) {
        #pragma unroll
        for (int i = 0; i < 2; ++i) {
            int gi = tid + (i << 8);
            int row = gi >> 2, kg = gi & 3;
            int pg = kg ^ ((row >> 1) & 3);
            uint4 u;
            u.x = pack_bf16(ra0[i].x, ra0[i].y);
            u.y = pack_bf16(ra0[i].z, ra0[i].w);
            u.z = pack_bf16(ra1[i].x, ra1[i].y);
            u.w = pack_bf16(ra1[i].z, ra1[i].w);
            *reinterpret_cast<uint4*>(&AsU[s][(row << 4) + (pg << 2)]) = u;
        }
        {
            int pg = wg ^ (wk & 7);
            uint4 u;
            u.x = pack_bf16(rw0.x, rw0.y);
            u.y = pack_bf16(rw0.z, rw0.w);
            u.z = pack_bf16(rw1.x, rw1.y);
            u.w = pack_bf16(rw1.z, rw1.w);
            *reinterpret_cast<uint4*>(&WsU[s][(wk << 5) + (pg << 2)]) = u;
        }
    };

    const int hi   = lane >> 4;
    const int rowL = (wm << 5) + (lane & 15);
    const int sA   = (rowL >> 1) & 3;
    const u32 aB0  = smaddr(&AsU[0][0]) + rowL * 64 + ((hi ^ sA) << 4);
    const int kL   = lane & 15;
    const int sB   = lane & 7;
    const int ng0  = (wn << 2) + hi;
    const u32 bB0  = smaddr(&WsU[0][0]) + kL * 128 + ((ng0 ^ sB) << 4);

    float acc[2][4][4] = {};

    auto compute = [&](int s) {
        const u32 aOff = (u32)(s * 8192);
        const u32 wOff = (u32)(s * 4096);
        #pragma unroll
        for (int kb = 0; kb < 2; ++kb) {
            const u32 ax = (aB0 ^ (kb << 5)) + aOff;
            const u32 bx = bB0 + wOff + (kb << 11);
            u32 a0[4], a1[4];
            LDSM4(a0[0], a0[1], a0[2], a0[3], ax);
            LDSM4(a1[0], a1[1], a1[2], a1[3], ax + 1024);
            #pragma unroll
            for (int nf16 = 0; nf16 < 2; ++nf16) {
                u32 b[4];
                LDSM4T(b[0], b[1], b[2], b[3], bx ^ (nf16 << 5));
                const int nfa = nf16 << 1;
                MMA_BF16(acc[0][nfa + 0], a0[0], a0[1], a0[2], a0[3], b[0], b[1]);
                MMA_BF16(acc[1][nfa + 0], a1[0], a1[1], a1[2], a1[3], b[0], b[1]);
                MMA_BF16(acc[0][nfa + 1], a0[0], a0[1], a0[2], a0[3], b[2], b[3]);
                MMA_BF16(acc[1][nfa + 1], a1[0], a1[1], a1[2], a1[3], b[2], b[3]);
            }
        }
    };

    load_regs_W(0);
#if __CUDA_ARCH__ >= 900
    cudaGridDependencySynchronize();
#endif
    load_regs_A(0);

    const int nk = K >> 5;
    store_smem(0);
    __syncthreads();

    int cur = 0;
    for (int t = 1; t <= nk; ++t) {
        const bool hn = (t < nk);
        if (hn) { load_regs_W(t << 5); load_regs_A(t << 5); }
        compute(cur);
        if (hn) {
            const int nxt = cur ^ 1;
            store_smem(nxt);
            __syncthreads();
            cur = nxt;
        }
    }

    #pragma unroll
    for (int mf = 0; mf < 2; ++mf) {
        #pragma unroll
        for (int nf = 0; nf < 4; ++nf) {
            const int col = bn + (wn << 5) + (nf << 3) + (tig << 1);
            float bx = 0.f, by = 0.f;
            if (bias) { bx = bias[col]; by = bias[col + 1]; }
            const int r0 = crow0 + (wm << 5) + (mf << 4) + g;
            const int r1 = r0 + 8;
            float v0 = acc[mf][nf][0] + bx, v1 = acc[mf][nf][1] + by;
            float v2 = acc[mf][nf][2] + bx, v3 = acc[mf][nf][3] + by;
            if (do_relu) {
                v0 = fmaxf(v0, 0.f); v1 = fmaxf(v1, 0.f);
                v2 = fmaxf(v2, 0.f); v3 = fmaxf(v3, 0.f);
            }
            float2 o01; o01.x = v0; o01.y = v1;
            float2 o23; o23.x = v2; o23.y = v3;
            *reinterpret_cast<float2*>(C + (size_t)r0 * HH + col) = o01;
            *reinterpret_cast<float2*>(C + (size_t)r1 * HH + col) = o23;
        }
    }
}

// ---------------- pairwise abs kernel (R11, byte-identical) ----------------
#define ADD2(d,a,b)   asm("add.rn.f32x2 %0,%1,%2;"     : "=l"(d) : "l"(a), "l"(b))
#define FMA2(d,a,b,c) asm("fma.rn.f32x2 %0,%1,%2,%3;"  : "=l"(d) : "l"(a), "l"(b), "l"(c))
#define ABS_MASK 0x7FFFFFFF7FFFFFFFULL
#define ASTR 132
#define CSTR 66

__global__ __launch_bounds__(512) void pair_abs_kernel(
    const float* __restrict__ Aa, const float* __restrict__ Cc,
    const float* __restrict__ w2, const float* __restrict__ b2p,
    float* __restrict__ out)
{
    __shared__ float  aD[2][32][ASTR];
    __shared__ float  cS[2][32][CSTR];
    __shared__ float2 wD[HH];
    __shared__ float  daS[64], dcS[64];

    const int tid = threadIdx.x;
    const int tx  = tid & 31;
    const int ty  = tid >> 5;
    const int i0  = blockIdx.x << 6, j0 = blockIdx.y << 6;
    const int b   = blockIdx.z;

    if (tid < HH) { float w = w2[tid]; wD[tid] = make_float2(w, w); }
    const float b2v = b2p[0];
#if __CUDA_ARCH__ >= 900
    cudaGridDependencySynchronize();
#endif

    const int sRow = tid >> 3;
    const int sh   = (tid & 7) << 2;

    const float* Ab = Aa + ((size_t)b * NNODE + i0) * HH;
    const float* Cb = Cc + ((size_t)b * NNODE + j0) * HH;

    ull acc0 = 0, acc1 = 0, acc2 = 0, acc3 = 0;
    float pa_dot = 0.f, pc_dot = 0.f;

    float4 av, cv;
    auto load_gmem = [&](int h0) {
        av = *reinterpret_cast<const float4*>(Ab + (size_t)sRow * HH + h0 + sh);
        cv = *reinterpret_cast<const float4*>(Cb + (size_t)sRow * HH + h0 + sh);
    };
    auto store_smem = [&](int s, int h0) {
        *reinterpret_cast<float2*>(&aD[s][sh+0][sRow<<1]) = make_float2(av.x, av.x);
        *reinterpret_cast<float2*>(&aD[s][sh+1][sRow<<1]) = make_float2(av.y, av.y);
        *reinterpret_cast<float2*>(&aD[s][sh+2][sRow<<1]) = make_float2(av.z, av.z);
        *reinterpret_cast<float2*>(&aD[s][sh+3][sRow<<1]) = make_float2(av.w, av.w);
        cS[s][sh+0][sRow] = cv.x;
        cS[s][sh+1][sRow] = cv.y;
        cS[s][sh+2][sRow] = cv.z;
        cS[s][sh+3][sRow] = cv.w;
        pa_dot += av.x*wD[h0+sh+0].x + av.y*wD[h0+sh+1].x
                + av.z*wD[h0+sh+2].x + av.w*wD[h0+sh+3].x;
        pc_dot += cv.x*wD[h0+sh+0].x + cv.y*wD[h0+sh+1].x
                + cv.z*wD[h0+sh+2].x + cv.w*wD[h0+sh+3].x;
    };

    load_gmem(0);
    __syncthreads();
    store_smem(0, 0);
    __syncthreads();

    int cur = 0;
    for (int t = 1; t <= 8; ++t) {
        const bool hn = (t < 8);
        if (hn) load_gmem(t << 5);
        const int hb = (t - 1) << 5;

        ulonglong2 aC0 = *reinterpret_cast<const ulonglong2*>(&aD[cur][0][ty << 3]);
        ulonglong2 aC1 = *reinterpret_cast<const ulonglong2*>(&aD[cur][0][(ty << 3) + 4]);
        ull cC = *reinterpret_cast<const ull*>(&cS[cur][0][tx << 1]);
        ull wC = *reinterpret_cast<const ull*>(&wD[hb]);
        #pragma unroll
        for (int h = 0; h < 32; ++h) {
            ulonglong2 aN0, aN1; ull cN, wN;
            if (h < 31) {
                aN0 = *reinterpret_cast<const ulonglong2*>(&aD[cur][h+1][ty << 3]);
                aN1 = *reinterpret_cast<const ulonglong2*>(&aD[cur][h+1][(ty << 3) + 4]);
                cN  = *reinterpret_cast<const ull*>(&cS[cur][h+1][tx << 1]);
                wN  = *reinterpret_cast<const ull*>(&wD[hb + h + 1]);
            }
            ull s0;
            ADD2(s0, aC0.x, cC); s0 &= ABS_MASK; FMA2(acc0, s0, wC, acc0);
            ADD2(s0, aC0.y, cC); s0 &= ABS_MASK; FMA2(acc1, s0, wC, acc1);
            ADD2(s0, aC1.x, cC); s0 &= ABS_MASK; FMA2(acc2, s0, wC, acc2);
            ADD2(s0, aC1.y, cC); s0 &= ABS_MASK; FMA2(acc3, s0, wC, acc3);
            aC0 = aN0; aC1 = aN1; cC = cN; wC = wN;
        }

        if (hn) {
            const int nxt = cur ^ 1;
            store_smem(nxt, t << 5);
            __syncthreads();
            cur = nxt;
        }
    }

    {
        float v = pa_dot, u = pc_dot;
        v += __shfl_xor_sync(0xffffffffu, v, 1);
        v += __shfl_xor_sync(0xffffffffu, v, 2);
        v += __shfl_xor_sync(0xffffffffu, v, 4);
        u += __shfl_xor_sync(0xffffffffu, u, 1);
        u += __shfl_xor_sync(0xffffffffu, u, 2);
        u += __shfl_xor_sync(0xffffffffu, u, 4);
        if ((tid & 7) == 0) { daS[sRow] = v; dcS[sRow] = u; }
    }
    __syncthreads();

    const float dc0 = dcS[(tx << 1) + 0];
    const float dc1 = dcS[(tx << 1) + 1];
    const int jcol = j0 + (tx << 1);
    ull accs[4] = {acc0, acc1, acc2, acc3};
    #pragma unroll
    for (int k = 0; k < 4; ++k) {
        const int i = (ty << 2) + k;
        const float dai = daS[i];
        float lo = __uint_as_float((u32)(accs[k] & 0xffffffffu));
        float hi = __uint_as_float((u32)(accs[k] >> 32));
        float2 o;
        o.x = 1.f / (1.f + __expf(-(0.5f * (dai + dc0 + lo) + b2v)));
        o.y = 1.f / (1.f + __expf(-(0.5f * (dai + dc1 + hi) + b2v)));
        *reinterpret_cast<float2*>(out + ((size_t)b * NNODE + i0 + i) * NNODE + jcol) = o;
    }
}

// ---------------- invariance reduction: float4-coalesced, 64 blocks ----------------
__global__ __launch_bounds__(256) void reduce_all(
    const float* __restrict__ causal, float* __restrict__ inv)
{
#if __CUDA_ARCH__ >= 900
    cudaGridDependencySynchronize();
#endif
    // each thread: 4 consecutive pairs via float4; 64 blocks * 256 thr * 4 = 65536
    const int p4 = (blockIdx.x * 256 + threadIdx.x) << 2;
    float4 x[8];
    #pragma unroll
    for (int b = 0; b < 8; ++b)
        x[b] = *reinterpret_cast<const float4*>(causal + (size_t)b * NMAT + p4);

    float stab = 0.f, sd = 0.f;
    #pragma unroll
    for (int e = 0; e < 4; ++e) {
        float v[8];
        #pragma unroll
        for (int b = 0; b < 8; ++b)
            v[b] = (e == 0) ? x[b].x : (e == 1) ? x[b].y : (e == 2) ? x[b].z : x[b].w;
        float s = 0.f;
        #pragma unroll
        for (int b = 0; b < 8; ++b) { stab += fabsf(v[b] - v[(b + 7) & 7]); s += v[b]; }
        const float m = s * 0.125f;
        float var = 0.f;
        #pragma unroll
        for (int b = 0; b < 8; ++b) { float d = v[b] - m; var = fmaf(d, d, var); }
        sd += sqrtf(var * (1.f / 7.f));   // ddof=1
    }

    #pragma unroll
    for (int o = 16; o; o >>= 1) {
        stab += __shfl_down_sync(0xffffffffu, stab, o);
        sd   += __shfl_down_sync(0xffffffffu, sd, o);
    }
    __shared__ float sm[8][2];
    const int wid = threadIdx.x >> 5, lane = threadIdx.x & 31;
    if (lane == 0) { sm[wid][0] = stab; sm[wid][1] = sd; }
    __syncthreads();
    if (threadIdx.x == 0) {
        float a = 0.f, c = 0.f;
        #pragma unroll
        for (int w = 0; w < 8; ++w) { a += sm[w][0]; c += sm[w][1]; }
        g_partial[blockIdx.x * 2 + 0] = a;
        g_partial[blockIdx.x * 2 + 1] = c;
    }

    __shared__ int isLast;
    __threadfence();
    if (threadIdx.x == 0) {
        u32 cdone = atomicAdd(&g_cnt, 1u);
        isLast = (cdone == 63u) ? 1 : 0;
    }
    __syncthreads();
    if (isLast) {
        float a = 0.f, c = 0.f;
        if (threadIdx.x < 64) {
            a = g_partial[threadIdx.x * 2 + 0];
            c = g_partial[threadIdx.x * 2 + 1];
        }
        #pragma unroll
        for (int o = 16; o; o >>= 1) {
            a += __shfl_down_sync(0xffffffffu, a, o);
            c += __shfl_down_sync(0xffffffffu, c, o);
        }
        if (lane == 0) { sm[wid][0] = a; sm[wid][1] = c; }
        __syncthreads();
        if (threadIdx.x == 0) {
            float sa = sm[0][0] + sm[1][0];
            float sc = sm[0][1] + sm[1][1];
            const float stability   = sa / (8.f * 65536.f);
            const float consistency = sc / 65536.f;
            inv[0] = 1.f - (stability + consistency) * 0.5f;
            g_cnt = 0u;
        }
    }
}

// ---------------- launch (PDL-chained, R11 layout) ----------------
static inline void set_pdl(cudaLaunchConfig_t& cfg, cudaLaunchAttribute* attr) {
    attr[0].id = cudaLaunchAttributeProgrammaticStreamSerialization;
    attr[0].val.programmaticStreamSerializationAllowed = 1;
    cfg.attrs = attr;
    cfg.numAttrs = 1;
}

extern "C" void kernel_launch(void* const* d_in, const int* in_sizes, int n_in,
                              void* d_out, int out_size)
{
    const float* img    = (const float*)d_in[0];
    const float* txt    = (const float*)d_in[1];
    const float* ft_W1  = (const float*)d_in[2];
    const float* ft_b1  = (const float*)d_in[3];
    const float* ft_W2  = (const float*)d_in[4];
    const float* ft_b2  = (const float*)d_in[5];
    const float* sl_W1a = (const float*)d_in[6];
    const float* sl_W1b = (const float*)d_in[7];
    const float* sl_b1  = (const float*)d_in[8];
    const float* sl_W2  = (const float*)d_in[9];
    const float* sl_b2  = (const float*)d_in[10];
    const float* cn_W1a = (const float*)d_in[11];
    const float* cn_W1b = (const float*)d_in[12];
    const float* cn_b1  = (const float*)d_in[13];
    const float* cn_W2  = (const float*)d_in[14];
    const float* cn_b2  = (const float*)d_in[15];

    float* outp      = (float*)d_out;
    float* structure = outp;
    float* causal    = outp + OUT_MAT;
    float* inv       = outp + 2 * OUT_MAT;

    float *x1, *h, *ac;
    cudaGetSymbolAddress((void**)&x1, g_x1);
    cudaGetSymbolAddress((void**)&h,  g_h);
    cudaGetSymbolAddress((void**)&ac, g_ac);

    const dim3 gemm_grid(M2 / 128, HH / 64);            // 32 x 4 = 128 blocks
    const dim3 pair_grid(NNODE / 64, NNODE / 64, BB);   // 4 x 4 x 8 = 128 blocks

    cudaLaunchAttribute attr[1];
    cudaLaunchConfig_t cfg{};
    cfg.stream = 0;
    cfg.dynamicSmemBytes = 0;

    gemm2_bf16<<<gemm_grid, 256>>>(img, txt, ft_W1, ft_W1, ft_b1, ft_b1, x1, FF, 1);

    cfg.gridDim = gemm_grid; cfg.blockDim = dim3(256);
    set_pdl(cfg, attr);
    cudaLaunchKernelEx(&cfg, gemm2_bf16,
        (const float*)x1, (const float*)(x1 + (size_t)MM * HH),
        ft_W2, ft_W2, ft_b2, ft_b2, h, HH, 0);

    cudaLaunchKernelEx(&cfg, gemm2_bf16,
        (const float*)h, (const float*)(h + (size_t)MM * HH),
        sl_W1a, sl_W1b, sl_b1, (const float*)nullptr, ac, HH, 0);

    cfg.gridDim = pair_grid; cfg.blockDim = dim3(512);
    cudaLaunchKernelEx(&cfg, pair_abs_kernel,
        (const float*)ac, (const float*)(ac + (size_t)MM * HH), sl_W2, sl_b2, structure);

    cfg.gridDim = gemm_grid; cfg.blockDim = dim3(256);
    cudaLaunchKernelEx(&cfg, gemm2_bf16,
        (const float*)structure, (const float*)structure,
        cn_W1a, cn_W1b, cn_b1, (const float*)nullptr, ac, HH, 0);

    cfg.gridDim = pair_grid; cfg.blockDim = dim3(512);
    cudaLaunchKernelEx(&cfg, pair_abs_kernel,
        (const float*)ac, (const float*)(ac + (size_t)MM * HH), cn_W2, cn_b2, causal);

    cfg.gridDim = dim3(64); cfg.blockDim = dim3(256);
    cudaLaunchKernelEx(&cfg, reduce_all, (const float*)causal, inv);
}